// round 15
// baseline (speedup 1.0000x reference)
#include <cuda_runtime.h>
#include <cuda_fp16.h>
#include <cstdint>

// Problem shape (fixed by setup_inputs): B=4, N=4096, coords [B,N,3] f32, radii [B,N] f32 in [0,1).
#define BB 4
#define NN 4096
#define TILE_I 128
#define NSPLIT 16
#define JCHUNK (NN / NSPLIT)   // 256 j's per block
#define JPAIRS (JCHUNK / 2)    // 128 packed j-pairs
#define GSZ 16                 // points per bounding group
#define GPSP (JCHUNK / GSZ)    // 16 groups per split
#define NBIN 4096              // 12-bit Morton bins per batch
#define NGROUP (BB * (NN / TILE_I))   // 128 (b,itile) reduction groups

// Scratch (__device__ globals; zero-initialized; no allocs allowed).
__device__ float4 g_spts[BB * NN];    // Morton-sorted (x,y,z,r)
__device__ int    g_sidx[BB * NN];    // sorted pos -> original batch-local index
__device__ float  g_part[(size_t)NSPLIT * BB * NN * 3];
__device__ int    g_done[NGROUP];     // winner resets -> replay-safe

// ---- packed-math helpers ----
#define PACK2(out, lo, hi)   asm("mov.b64 %0, {%1, %2};" : "=l"(out) : "f"(lo), "f"(hi))
#define UNPACK2(lo, hi, in)  asm("mov.b64 {%0, %1}, %2;" : "=f"(lo), "=f"(hi) : "l"(in))
#define ADD2(out, a, b)      asm("add.rn.f32x2 %0, %1, %2;" : "=l"(out) : "l"(a), "l"(b))
#define MUL2(out, a, b)      asm("mul.rn.f32x2 %0, %1, %2;" : "=l"(out) : "l"(a), "l"(b))
#define FMA2(out, a, b, c)   asm("fma.rn.f32x2 %0, %1, %2, %3;" : "=l"(out) : "l"(a), "l"(b), "l"(c))
#define LDS64(out, addr)     asm("ld.shared.b64 %0, [%1];" : "=l"(out) : "r"(addr))
#define LDS32(out, addr)     asm("ld.shared.b32 %0, [%1];" : "=r"(out) : "r"(addr))
#define SQRTA(out, in)       asm("sqrt.approx.f32 %0, %1;" : "=f"(out) : "f"(in))
#define CVTH2(out, hi, lo)   asm("cvt.rn.f16x2.f32 %0, %1, %2;" : "=r"(out) : "f"(hi), "f"(lo))
#define HADD2(out, a, b)     asm("add.rn.f16x2 %0, %1, %2;" : "=r"(out) : "r"(a), "r"(b))
#define HSUB2(out, a, b)     asm("sub.rn.f16x2 %0, %1, %2;" : "=r"(out) : "r"(a), "r"(b))
#define HMIN2(out, a, b)     asm("min.f16x2 %0, %1, %2;"    : "=r"(out) : "r"(a), "r"(b))
#define HMAX2(out, a, b)     asm("max.f16x2 %0, %1, %2;"    : "=r"(out) : "r"(a), "r"(b))
#define HFMA2(out, a, b, c)  asm("fma.rn.f16x2 %0, %1, %2, %3;" : "=r"(out) : "r"(a), "r"(b), "r"(c))

#define H2_ONE  0x3C003C00u
#define H2_NEG1 0xBC00BC00u
#define H2_ZERO 0x00000000u

__device__ __forceinline__ uint32_t spread4(uint32_t x) {
    return (x & 1u) | ((x & 2u) << 2) | ((x & 4u) << 4) | ((x & 8u) << 6);
}
__device__ __forceinline__ uint32_t qcell(float v) {
    int c = (int)((v + 22.4f) * (1.0f / 2.8f));
    return (uint32_t)min(15, max(0, c));
}

// ---- K1: per-batch full counting sort (bin + hist + scan + scatter), 1 block/batch ----
__global__ __launch_bounds__(1024)
void k_sort(const float* __restrict__ coords, const float* __restrict__ radii) {
    __shared__ int s_hist[NBIN];   // 16KB: histogram, then cursors in-place
    __shared__ int wsum[32];
    const int b = blockIdx.x, t = threadIdx.x;

    #pragma unroll
    for (int k = 0; k < NBIN / 1024; k++) s_hist[k * 1024 + t] = 0;
    __syncthreads();

    // Pass 1: load 4 points into registers, bin, smem histogram.
    float4 pt[4];
    int    bin_[4];
    #pragma unroll
    for (int k = 0; k < 4; k++) {
        const int lp = k * 1024 + t;         // batch-local index
        const int p  = b * NN + lp;
        const float x = coords[3 * p], y = coords[3 * p + 1], z = coords[3 * p + 2];
        pt[k]   = make_float4(x, y, z, radii[p]);
        bin_[k] = (int)(spread4(qcell(x)) | (spread4(qcell(y)) << 1) | (spread4(qcell(z)) << 2));
        atomicAdd(&s_hist[bin_[k]], 1);
    }
    __syncthreads();

    // Exclusive scan of 4096 bins, 4 consecutive per thread (each thread owns its bins).
    const int c0 = s_hist[4 * t], c1 = s_hist[4 * t + 1], c2 = s_hist[4 * t + 2], c3 = s_hist[4 * t + 3];
    const int s = c0 + c1 + c2 + c3;
    const int lane = t & 31, wid = t >> 5;
    int v = s;
    #pragma unroll
    for (int off = 1; off < 32; off <<= 1) {
        int u = __shfl_up_sync(0xffffffffu, v, off);
        if (lane >= off) v += u;
    }
    if (lane == 31) wsum[wid] = v;
    __syncthreads();
    if (wid == 0) {
        int w = wsum[lane];
        #pragma unroll
        for (int off = 1; off < 32; off <<= 1) {
            int u = __shfl_up_sync(0xffffffffu, w, off);
            if (lane >= off) w += u;
        }
        wsum[lane] = w;
    }
    __syncthreads();
    const int pref = v - s + (wid > 0 ? wsum[wid - 1] : 0);
    s_hist[4 * t]     = pref;                 // own bins only: no race
    s_hist[4 * t + 1] = pref + c0;
    s_hist[4 * t + 2] = pref + c0 + c1;
    s_hist[4 * t + 3] = pref + c0 + c1 + c2;
    __syncthreads();

    // Pass 2: scatter from registers via smem cursors.
    #pragma unroll
    for (int k = 0; k < 4; k++) {
        const int pos = atomicAdd(&s_hist[bin_[k]], 1);
        g_spts[b * NN + pos] = pt[k];
        g_sidx[b * NN + pos] = k * 1024 + t;
    }
}

// ---- K2: group-culled main + fused last-block reduction (identical to R13) ----
__global__ __launch_bounds__(TILE_I, 12)
void steric_fused(float* __restrict__ out) {
    __shared__ __align__(16) float    snx[JCHUNK];
    __shared__ __align__(16) float    sny[JCHUNK];
    __shared__ __align__(16) float    snz[JCHUNK];
    __shared__ __align__(16) uint32_t srh[JPAIRS];
    __shared__ __align__(16) float4   sgb[GPSP];     // (-cx,-cy,-cz, (2+rg)^2)
    __shared__ int s_ticket;

    const int bidx  = blockIdx.x;
    const int split = bidx % NSPLIT;
    const int itile = (bidx / NSPLIT) % (NN / TILE_I);
    const int b     = bidx / (NSPLIT * (NN / TILE_I));
    const int group = b * (NN / TILE_I) + itile;
    const int tid   = threadIdx.x;

    const int jbase = b * NN + split * JCHUNK;
    for (int k = tid; k < JPAIRS; k += TILE_I) {
        const float4 p0 = g_spts[jbase + 2 * k];
        const float4 p1 = g_spts[jbase + 2 * k + 1];
        snx[2 * k] = -p0.x; snx[2 * k + 1] = -p1.x;
        sny[2 * k] = -p0.y; sny[2 * k + 1] = -p1.y;
        snz[2 * k] = -p0.z; snz[2 * k + 1] = -p1.z;
        uint32_t rp;
        CVTH2(rp, p1.w, p0.w);
        srh[k] = rp;
    }
    __syncthreads();

    // In-block group bounds from staged (negated) coords. Exact conservative cull:
    // d(i,C) >= 2+rg  =>  d(i,j) >= 2 > target  =>  pen = 0 for the whole group.
    if (tid < GPSP) {
        const int s0 = tid * GSZ;
        float cx = 0.f, cy = 0.f, cz = 0.f;
        #pragma unroll
        for (int k = 0; k < GSZ; k++) { cx += snx[s0 + k]; cy += sny[s0 + k]; cz += snz[s0 + k]; }
        cx *= (1.0f / GSZ); cy *= (1.0f / GSZ); cz *= (1.0f / GSZ);
        float m2 = 0.f;
        #pragma unroll
        for (int k = 0; k < GSZ; k++) {
            const float dx = snx[s0 + k] - cx, dy = sny[s0 + k] - cy, dz = snz[s0 + k] - cz;
            m2 = fmaxf(m2, dx * dx + dy * dy + dz * dz);
        }
        const float thr = 2.0f + sqrtf(m2) * 1.001f + 1e-3f;    // pad swallows rounding
        sgb[tid] = make_float4(cx, cy, cz, thr * thr);           // negated centroid
    }
    __syncthreads();

    const int is = itile * TILE_I + tid;   // sorted position in batch
    const float4 q = g_spts[b * NN + is];

    unsigned long long xi2, yi2, zi2;
    PACK2(xi2, q.x, q.x);
    PACK2(yi2, q.y, q.y);
    PACK2(zi2, q.z, q.z);
    uint32_t ri2;
    CVTH2(ri2, q.w, q.w);

    const unsigned int anx = (unsigned int)__cvta_generic_to_shared(snx);
    const unsigned int any_ = (unsigned int)__cvta_generic_to_shared(sny);
    const unsigned int anz = (unsigned int)__cvta_generic_to_shared(snz);
    const unsigned int arh = (unsigned int)__cvta_generic_to_shared(srh);

    uint32_t axh = H2_ZERO, ayh = H2_ZERO, azh = H2_ZERO;

    for (int g = 0; g < GPSP; g++) {
        const float4 G = sgb[g];
        const float gx = q.x + G.x, gy = q.y + G.y, gz = q.z + G.z;   // q - centroid
        const float d2c = gx * gx + gy * gy + gz * gz;
        if (d2c >= G.w) continue;

        const int k0 = g * (GSZ / 2);
        #pragma unroll
        for (int kk = k0; kk < k0 + GSZ / 2; kk++) {
            unsigned long long nxp, nyp, nzp;
            LDS64(nxp, anx + 8u * kk);
            LDS64(nyp, any_ + 8u * kk);
            LDS64(nzp, anz + 8u * kk);

            unsigned long long dxp, dyp, dzp, d2p;
            ADD2(dxp, xi2, nxp);
            ADD2(dyp, yi2, nyp);
            ADD2(dzp, zi2, nzp);
            MUL2(d2p, dxp, dxp);
            FMA2(d2p, dyp, dyp, d2p);
            FMA2(d2p, dzp, dzp, d2p);

            float d2lo, d2hi;
            UNPACK2(d2lo, d2hi, d2p);

            // EXACT skip: radii in [0,1) => target < 2 => pen>0 only if d2 < 4.
            if (fminf(d2lo, d2hi) < 4.0f) {
                float dx0, dx1, dy0, dy1, dz0, dz1;
                UNPACK2(dx0, dx1, dxp);
                UNPACK2(dy0, dy1, dyp);
                UNPACK2(dz0, dz1, dzp);

                float d0, d1;
                SQRTA(d0, d2lo);    // sqrt.approx(0)==0: diagonal safe (clip(0)=0)
                SQRTA(d1, d2hi);

                uint32_t dh, dxh, dyh, dzh, rp, t, pen;
                CVTH2(dh,  d1,  d0);
                CVTH2(dxh, dx1, dx0);
                CVTH2(dyh, dy1, dy0);
                CVTH2(dzh, dz1, dz0);
                LDS32(rp, arh + 4u * kk);

                HADD2(t, ri2, rp);
                HMAX2(t, t, H2_ONE);
                HSUB2(pen, t, dh);
                HMAX2(pen, pen, H2_ZERO);

                uint32_t cx, cy, cz;
                HMAX2(cx, dxh, H2_NEG1); HMIN2(cx, cx, H2_ONE);
                HMAX2(cy, dyh, H2_NEG1); HMIN2(cy, cy, H2_ONE);
                HMAX2(cz, dzh, H2_NEG1); HMIN2(cz, cz, H2_ONE);

                HFMA2(axh, pen, cx, axh);
                HFMA2(ayh, pen, cy, ayh);
                HFMA2(azh, pen, cz, azh);
            }
        }
    }

    const __half2 hax = *reinterpret_cast<__half2*>(&axh);
    const __half2 hay = *reinterpret_cast<__half2*>(&ayh);
    const __half2 haz = *reinterpret_cast<__half2*>(&azh);
    const float ax = __low2float(hax) + __high2float(hax);
    const float ay = __low2float(hay) + __high2float(hay);
    const float az = __low2float(haz) + __high2float(haz);

    const size_t idx3 = ((size_t)b * NN + is) * 3;
    float* dst = g_part + (size_t)split * BB * NN * 3 + idx3;
    dst[0] = ax; dst[1] = ay; dst[2] = az;

    // Last-block-done reduction (fixed split order 0..15).
    __threadfence();
    if (tid == 0) s_ticket = atomicAdd(&g_done[group], 1);
    __syncthreads();
    if (s_ticket == NSPLIT - 1) {
        __threadfence();
        float sx = 0.f, sy = 0.f, sz = 0.f;
        #pragma unroll
        for (int sp = 0; sp < NSPLIT; sp++) {
            const float* p = g_part + (size_t)sp * BB * NN * 3 + idx3;
            sx += p[0]; sy += p[1]; sz += p[2];
        }
        const float k = 0.1f / (float)NN;
        const size_t o3 = ((size_t)b * NN + g_sidx[b * NN + is]) * 3;
        out[o3]     = fmaf(k, sx, q.x);
        out[o3 + 1] = fmaf(k, sy, q.y);
        out[o3 + 2] = fmaf(k, sz, q.z);
        if (tid == 0) g_done[group] = 0;   // reset for next execution
    }
}

extern "C" void kernel_launch(void* const* d_in, const int* in_sizes, int n_in,
                              void* d_out, int out_size) {
    const float* coords = (const float*)d_in[0];
    const float* radii  = (const float*)d_in[1];
    float* out = (float*)d_out;

    int B = in_sizes[1] / NN;   // radii elems = B*N
    if (B < 1) B = 1;
    if (B > BB) B = BB;

    k_sort      <<<B, 1024>>>(coords, radii);
    const int grid = B * (NN / TILE_I) * NSPLIT;
    steric_fused<<<grid, TILE_I>>>(out);
}

// round 16
// speedup vs baseline: 1.4366x; 1.4366x over previous
#include <cuda_runtime.h>
#include <cuda_fp16.h>
#include <cstdint>

// Problem shape (fixed by setup_inputs): B=4, N=4096, coords [B,N,3] f32, radii [B,N] f32 in [0,1).
#define BB 4
#define NN 4096
#define TILE_I 128
#define NSPLIT 8
#define JCHUNK (NN / NSPLIT)   // 512 j's per block
#define JPAIRS (JCHUNK / 2)    // 256 packed j-pairs
#define GSZ 16                 // points per bounding group
#define GPSP (JCHUNK / GSZ)    // 32 groups per split
#define NBIN 4096              // 12-bit Morton bins per batch
#define NGROUP (BB * (NN / TILE_I))   // 128 (b,itile) reduction groups

// Scratch (__device__ globals; zero-initialized; no allocs allowed).
__device__ float4 g_spts[BB * NN];    // Morton-sorted (x,y,z,r)
__device__ int    g_sidx[BB * NN];    // sorted pos -> original batch-local index
__device__ float  g_part[(size_t)NSPLIT * BB * NN * 3];
__device__ int    g_done[NGROUP];     // winner resets -> replay-safe

// ---- packed-math helpers ----
#define PACK2(out, lo, hi)   asm("mov.b64 %0, {%1, %2};" : "=l"(out) : "f"(lo), "f"(hi))
#define UNPACK2(lo, hi, in)  asm("mov.b64 {%0, %1}, %2;" : "=f"(lo), "=f"(hi) : "l"(in))
#define ADD2(out, a, b)      asm("add.rn.f32x2 %0, %1, %2;" : "=l"(out) : "l"(a), "l"(b))
#define MUL2(out, a, b)      asm("mul.rn.f32x2 %0, %1, %2;" : "=l"(out) : "l"(a), "l"(b))
#define FMA2(out, a, b, c)   asm("fma.rn.f32x2 %0, %1, %2, %3;" : "=l"(out) : "l"(a), "l"(b), "l"(c))
#define LDS64(out, addr)     asm("ld.shared.b64 %0, [%1];" : "=l"(out) : "r"(addr))
#define LDS32(out, addr)     asm("ld.shared.b32 %0, [%1];" : "=r"(out) : "r"(addr))
#define SQRTA(out, in)       asm("sqrt.approx.f32 %0, %1;" : "=f"(out) : "f"(in))
#define CVTH2(out, hi, lo)   asm("cvt.rn.f16x2.f32 %0, %1, %2;" : "=r"(out) : "f"(hi), "f"(lo))
#define HADD2(out, a, b)     asm("add.rn.f16x2 %0, %1, %2;" : "=r"(out) : "r"(a), "r"(b))
#define HSUB2(out, a, b)     asm("sub.rn.f16x2 %0, %1, %2;" : "=r"(out) : "r"(a), "r"(b))
#define HMIN2(out, a, b)     asm("min.f16x2 %0, %1, %2;"    : "=r"(out) : "r"(a), "r"(b))
#define HMAX2(out, a, b)     asm("max.f16x2 %0, %1, %2;"    : "=r"(out) : "r"(a), "r"(b))
#define HFMA2(out, a, b, c)  asm("fma.rn.f16x2 %0, %1, %2, %3;" : "=r"(out) : "r"(a), "r"(b), "r"(c))

#define H2_ONE  0x3C003C00u
#define H2_NEG1 0xBC00BC00u
#define H2_ZERO 0x00000000u

__device__ __forceinline__ uint32_t spread4(uint32_t x) {
    return (x & 1u) | ((x & 2u) << 2) | ((x & 4u) << 4) | ((x & 8u) << 6);
}
__device__ __forceinline__ uint32_t qcell(float v) {
    int c = (int)((v + 22.4f) * (1.0f / 2.8f));
    return (uint32_t)min(15, max(0, c));
}

// ---- K1: per-batch full counting sort (bin + hist + scan + scatter), 1 block/batch ----
__global__ __launch_bounds__(1024)
void k_sort(const float* __restrict__ coords, const float* __restrict__ radii) {
    __shared__ int s_hist[NBIN];   // 16KB: histogram, then cursors in-place
    __shared__ int wsum[32];
    const int b = blockIdx.x, t = threadIdx.x;

    #pragma unroll
    for (int k = 0; k < NBIN / 1024; k++) s_hist[k * 1024 + t] = 0;
    __syncthreads();

    // Pass 1: load 4 points into registers, bin, smem histogram.
    float4 pt[4];
    int    bin_[4];
    #pragma unroll
    for (int k = 0; k < 4; k++) {
        const int lp = k * 1024 + t;         // batch-local index
        const int p  = b * NN + lp;
        const float x = coords[3 * p], y = coords[3 * p + 1], z = coords[3 * p + 2];
        pt[k]   = make_float4(x, y, z, radii[p]);
        bin_[k] = (int)(spread4(qcell(x)) | (spread4(qcell(y)) << 1) | (spread4(qcell(z)) << 2));
        atomicAdd(&s_hist[bin_[k]], 1);
    }
    __syncthreads();

    // Exclusive scan of 4096 bins, 4 consecutive per thread (each thread owns its bins).
    const int c0 = s_hist[4 * t], c1 = s_hist[4 * t + 1], c2 = s_hist[4 * t + 2], c3 = s_hist[4 * t + 3];
    const int s = c0 + c1 + c2 + c3;
    const int lane = t & 31, wid = t >> 5;
    int v = s;
    #pragma unroll
    for (int off = 1; off < 32; off <<= 1) {
        int u = __shfl_up_sync(0xffffffffu, v, off);
        if (lane >= off) v += u;
    }
    if (lane == 31) wsum[wid] = v;
    __syncthreads();
    if (wid == 0) {
        int w = wsum[lane];
        #pragma unroll
        for (int off = 1; off < 32; off <<= 1) {
            int u = __shfl_up_sync(0xffffffffu, w, off);
            if (lane >= off) w += u;
        }
        wsum[lane] = w;
    }
    __syncthreads();
    const int pref = v - s + (wid > 0 ? wsum[wid - 1] : 0);
    s_hist[4 * t]     = pref;                 // own bins only: no race
    s_hist[4 * t + 1] = pref + c0;
    s_hist[4 * t + 2] = pref + c0 + c1;
    s_hist[4 * t + 3] = pref + c0 + c1 + c2;
    __syncthreads();

    // Pass 2: scatter from registers via smem cursors.
    #pragma unroll
    for (int k = 0; k < 4; k++) {
        const int pos = atomicAdd(&s_hist[bin_[k]], 1);
        g_spts[b * NN + pos] = pt[k];
        g_sidx[b * NN + pos] = k * 1024 + t;
    }
}

// ---- K2: group-culled main + fused last-block reduction ----
__global__ __launch_bounds__(TILE_I, 12)
void steric_fused(float* __restrict__ out) {
    __shared__ __align__(16) float    snx[JCHUNK];
    __shared__ __align__(16) float    sny[JCHUNK];
    __shared__ __align__(16) float    snz[JCHUNK];
    __shared__ __align__(16) uint32_t srh[JPAIRS];
    __shared__ __align__(16) float4   sgb[GPSP];     // (-cx,-cy,-cz, (2+rg)^2)
    __shared__ int s_ticket;

    const int bidx  = blockIdx.x;
    const int split = bidx % NSPLIT;
    const int itile = (bidx / NSPLIT) % (NN / TILE_I);
    const int b     = bidx / (NSPLIT * (NN / TILE_I));
    const int group = b * (NN / TILE_I) + itile;
    const int tid   = threadIdx.x;

    const int jbase = b * NN + split * JCHUNK;
    for (int k = tid; k < JPAIRS; k += TILE_I) {
        const float4 p0 = g_spts[jbase + 2 * k];
        const float4 p1 = g_spts[jbase + 2 * k + 1];
        snx[2 * k] = -p0.x; snx[2 * k + 1] = -p1.x;
        sny[2 * k] = -p0.y; sny[2 * k + 1] = -p1.y;
        snz[2 * k] = -p0.z; snz[2 * k + 1] = -p1.z;
        uint32_t rp;
        CVTH2(rp, p1.w, p0.w);
        srh[k] = rp;
    }
    __syncthreads();

    // In-block group bounds from staged (negated) coords. Exact conservative cull:
    // d(i,C) >= 2+rg  =>  d(i,j) >= 2 > target  =>  pen = 0 for the whole group.
    if (tid < GPSP) {
        const int s0 = tid * GSZ;
        float cx = 0.f, cy = 0.f, cz = 0.f;
        #pragma unroll
        for (int k = 0; k < GSZ; k++) { cx += snx[s0 + k]; cy += sny[s0 + k]; cz += snz[s0 + k]; }
        cx *= (1.0f / GSZ); cy *= (1.0f / GSZ); cz *= (1.0f / GSZ);
        float m2 = 0.f;
        #pragma unroll
        for (int k = 0; k < GSZ; k++) {
            const float dx = snx[s0 + k] - cx, dy = sny[s0 + k] - cy, dz = snz[s0 + k] - cz;
            m2 = fmaxf(m2, dx * dx + dy * dy + dz * dz);
        }
        const float thr = 2.0f + sqrtf(m2) * 1.001f + 1e-3f;    // pad swallows rounding
        sgb[tid] = make_float4(cx, cy, cz, thr * thr);           // negated centroid
    }
    __syncthreads();

    const int is = itile * TILE_I + tid;   // sorted position in batch
    const float4 q = g_spts[b * NN + is];

    unsigned long long xi2, yi2, zi2;
    PACK2(xi2, q.x, q.x);
    PACK2(yi2, q.y, q.y);
    PACK2(zi2, q.z, q.z);
    uint32_t ri2;
    CVTH2(ri2, q.w, q.w);

    const unsigned int anx = (unsigned int)__cvta_generic_to_shared(snx);
    const unsigned int any_ = (unsigned int)__cvta_generic_to_shared(sny);
    const unsigned int anz = (unsigned int)__cvta_generic_to_shared(snz);
    const unsigned int arh = (unsigned int)__cvta_generic_to_shared(srh);

    uint32_t axh = H2_ZERO, ayh = H2_ZERO, azh = H2_ZERO;

    for (int g = 0; g < GPSP; g++) {
        const float4 G = sgb[g];
        const float gx = q.x + G.x, gy = q.y + G.y, gz = q.z + G.z;   // q - centroid
        const float d2c = gx * gx + gy * gy + gz * gz;
        if (d2c >= G.w) continue;

        const int k0 = g * (GSZ / 2);
        #pragma unroll
        for (int kk = k0; kk < k0 + GSZ / 2; kk++) {
            unsigned long long nxp, nyp, nzp;
            LDS64(nxp, anx + 8u * kk);
            LDS64(nyp, any_ + 8u * kk);
            LDS64(nzp, anz + 8u * kk);

            unsigned long long dxp, dyp, dzp, d2p;
            ADD2(dxp, xi2, nxp);
            ADD2(dyp, yi2, nyp);
            ADD2(dzp, zi2, nzp);
            MUL2(d2p, dxp, dxp);
            FMA2(d2p, dyp, dyp, d2p);
            FMA2(d2p, dzp, dzp, d2p);

            float d2lo, d2hi;
            UNPACK2(d2lo, d2hi, d2p);

            // EXACT skip: radii in [0,1) => target < 2 => pen>0 only if d2 < 4.
            if (fminf(d2lo, d2hi) < 4.0f) {
                float dx0, dx1, dy0, dy1, dz0, dz1;
                UNPACK2(dx0, dx1, dxp);
                UNPACK2(dy0, dy1, dyp);
                UNPACK2(dz0, dz1, dzp);

                float d0, d1;
                SQRTA(d0, d2lo);    // sqrt.approx(0)==0: diagonal safe (clip(0)=0)
                SQRTA(d1, d2hi);

                uint32_t dh, dxh, dyh, dzh, rp, t, pen;
                CVTH2(dh,  d1,  d0);
                CVTH2(dxh, dx1, dx0);
                CVTH2(dyh, dy1, dy0);
                CVTH2(dzh, dz1, dz0);
                LDS32(rp, arh + 4u * kk);

                HADD2(t, ri2, rp);
                HMAX2(t, t, H2_ONE);
                HSUB2(pen, t, dh);
                HMAX2(pen, pen, H2_ZERO);

                uint32_t cx, cy, cz;
                HMAX2(cx, dxh, H2_NEG1); HMIN2(cx, cx, H2_ONE);
                HMAX2(cy, dyh, H2_NEG1); HMIN2(cy, cy, H2_ONE);
                HMAX2(cz, dzh, H2_NEG1); HMIN2(cz, cz, H2_ONE);

                HFMA2(axh, pen, cx, axh);
                HFMA2(ayh, pen, cy, ayh);
                HFMA2(azh, pen, cz, azh);
            }
        }
    }

    const __half2 hax = *reinterpret_cast<__half2*>(&axh);
    const __half2 hay = *reinterpret_cast<__half2*>(&ayh);
    const __half2 haz = *reinterpret_cast<__half2*>(&azh);
    const float ax = __low2float(hax) + __high2float(hax);
    const float ay = __low2float(hay) + __high2float(hay);
    const float az = __low2float(haz) + __high2float(haz);

    const size_t idx3 = ((size_t)b * NN + is) * 3;
    float* dst = g_part + (size_t)split * BB * NN * 3 + idx3;
    dst[0] = ax; dst[1] = ay; dst[2] = az;

    // Last-block-done reduction (fixed split order 0..7).
    __threadfence();
    if (tid == 0) s_ticket = atomicAdd(&g_done[group], 1);
    __syncthreads();
    if (s_ticket == NSPLIT - 1) {
        __threadfence();
        float sx = 0.f, sy = 0.f, sz = 0.f;
        #pragma unroll
        for (int sp = 0; sp < NSPLIT; sp++) {
            const float* p = g_part + (size_t)sp * BB * NN * 3 + idx3;
            sx += p[0]; sy += p[1]; sz += p[2];
        }
        const float k = 0.1f / (float)NN;
        const size_t o3 = ((size_t)b * NN + g_sidx[b * NN + is]) * 3;
        out[o3]     = fmaf(k, sx, q.x);
        out[o3 + 1] = fmaf(k, sy, q.y);
        out[o3 + 2] = fmaf(k, sz, q.z);
        if (tid == 0) g_done[group] = 0;   // reset for next execution
    }
}

extern "C" void kernel_launch(void* const* d_in, const int* in_sizes, int n_in,
                              void* d_out, int out_size) {
    const float* coords = (const float*)d_in[0];
    const float* radii  = (const float*)d_in[1];
    float* out = (float*)d_out;

    int B = in_sizes[1] / NN;   // radii elems = B*N
    if (B < 1) B = 1;
    if (B > BB) B = BB;

    k_sort      <<<B, 1024>>>(coords, radii);
    const int grid = B * (NN / TILE_I) * NSPLIT;
    steric_fused<<<grid, TILE_I>>>(out);
}

// round 17
// speedup vs baseline: 1.7172x; 1.1953x over previous
#include <cuda_runtime.h>
#include <cuda_fp16.h>
#include <cstdint>

// Problem shape (fixed by setup_inputs): B=4, N=4096, coords [B,N,3] f32, radii [B,N] f32 in [0,1).
#define BB 4
#define NN 4096
#define TILE_I 128
#define NSPLIT 8
#define JCHUNK (NN / NSPLIT)   // 512 j's per block
#define JPAIRS (JCHUNK / 2)    // 256 packed j-pairs
#define GSZ 16                 // points per bounding group
#define GPSP (JCHUNK / GSZ)    // 32 groups per split
#define NBIN 4096              // 12-bit Morton bins per batch
#define NGROUP (BB * (NN / TILE_I))   // 128 (b,itile) reduction groups

// Scratch (__device__ globals; zero-initialized; no allocs allowed).
__device__ float4 g_spts[BB * NN];    // Morton-sorted (x,y,z,r)
__device__ int    g_sidx[BB * NN];    // sorted pos -> original batch-local index
__device__ float  g_part[(size_t)NSPLIT * BB * NN * 3];
__device__ int    g_done[NGROUP];     // winner resets -> replay-safe

// ---- packed-math helpers ----
#define PACK2(out, lo, hi)   asm("mov.b64 %0, {%1, %2};" : "=l"(out) : "f"(lo), "f"(hi))
#define UNPACK2(lo, hi, in)  asm("mov.b64 {%0, %1}, %2;" : "=f"(lo), "=f"(hi) : "l"(in))
#define ADD2(out, a, b)      asm("add.rn.f32x2 %0, %1, %2;" : "=l"(out) : "l"(a), "l"(b))
#define MUL2(out, a, b)      asm("mul.rn.f32x2 %0, %1, %2;" : "=l"(out) : "l"(a), "l"(b))
#define FMA2(out, a, b, c)   asm("fma.rn.f32x2 %0, %1, %2, %3;" : "=l"(out) : "l"(a), "l"(b), "l"(c))
#define LDS64(out, addr)     asm("ld.shared.b64 %0, [%1];" : "=l"(out) : "r"(addr))
#define LDS32(out, addr)     asm("ld.shared.b32 %0, [%1];" : "=r"(out) : "r"(addr))
#define SQRTA(out, in)       asm("sqrt.approx.f32 %0, %1;" : "=f"(out) : "f"(in))
#define CVTH2(out, hi, lo)   asm("cvt.rn.f16x2.f32 %0, %1, %2;" : "=r"(out) : "f"(hi), "f"(lo))
#define HADD2(out, a, b)     asm("add.rn.f16x2 %0, %1, %2;" : "=r"(out) : "r"(a), "r"(b))
#define HSUB2(out, a, b)     asm("sub.rn.f16x2 %0, %1, %2;" : "=r"(out) : "r"(a), "r"(b))
#define HMIN2(out, a, b)     asm("min.f16x2 %0, %1, %2;"    : "=r"(out) : "r"(a), "r"(b))
#define HMAX2(out, a, b)     asm("max.f16x2 %0, %1, %2;"    : "=r"(out) : "r"(a), "r"(b))
#define HFMA2(out, a, b, c)  asm("fma.rn.f16x2 %0, %1, %2, %3;" : "=r"(out) : "r"(a), "r"(b), "r"(c))

#define H2_ONE  0x3C003C00u
#define H2_NEG1 0xBC00BC00u
#define H2_ZERO 0x00000000u

__device__ __forceinline__ uint32_t spread4(uint32_t x) {
    return (x & 1u) | ((x & 2u) << 2) | ((x & 4u) << 4) | ((x & 8u) << 6);
}
__device__ __forceinline__ uint32_t qcell(float v) {
    int c = (int)((v + 22.4f) * (1.0f / 2.8f));
    return (uint32_t)min(15, max(0, c));
}

// ---- K1: per-batch full counting sort (bin + hist + scan + scatter), 1 block/batch ----
__global__ __launch_bounds__(1024)
void k_sort(const float* __restrict__ coords, const float* __restrict__ radii) {
    __shared__ int s_hist[NBIN];   // 16KB: histogram, then cursors in-place
    __shared__ int wsum[32];
    const int b = blockIdx.x, t = threadIdx.x;

    #pragma unroll
    for (int k = 0; k < NBIN / 1024; k++) s_hist[k * 1024 + t] = 0;
    __syncthreads();

    // Pass 1: load 4 points into registers, bin, smem histogram.
    float4 pt[4];
    int    bin_[4];
    #pragma unroll
    for (int k = 0; k < 4; k++) {
        const int lp = k * 1024 + t;         // batch-local index
        const int p  = b * NN + lp;
        const float x = coords[3 * p], y = coords[3 * p + 1], z = coords[3 * p + 2];
        pt[k]   = make_float4(x, y, z, radii[p]);
        bin_[k] = (int)(spread4(qcell(x)) | (spread4(qcell(y)) << 1) | (spread4(qcell(z)) << 2));
        atomicAdd(&s_hist[bin_[k]], 1);
    }
    __syncthreads();

    // Exclusive scan of 4096 bins, 4 consecutive per thread (each thread owns its bins).
    const int c0 = s_hist[4 * t], c1 = s_hist[4 * t + 1], c2 = s_hist[4 * t + 2], c3 = s_hist[4 * t + 3];
    const int s = c0 + c1 + c2 + c3;
    const int lane = t & 31, wid = t >> 5;
    int v = s;
    #pragma unroll
    for (int off = 1; off < 32; off <<= 1) {
        int u = __shfl_up_sync(0xffffffffu, v, off);
        if (lane >= off) v += u;
    }
    if (lane == 31) wsum[wid] = v;
    __syncthreads();
    if (wid == 0) {
        int w = wsum[lane];
        #pragma unroll
        for (int off = 1; off < 32; off <<= 1) {
            int u = __shfl_up_sync(0xffffffffu, w, off);
            if (lane >= off) w += u;
        }
        wsum[lane] = w;
    }
    __syncthreads();
    const int pref = v - s + (wid > 0 ? wsum[wid - 1] : 0);
    s_hist[4 * t]     = pref;                 // own bins only: no race
    s_hist[4 * t + 1] = pref + c0;
    s_hist[4 * t + 2] = pref + c0 + c1;
    s_hist[4 * t + 3] = pref + c0 + c1 + c2;
    __syncthreads();

    // Pass 2: scatter from registers via smem cursors.
    #pragma unroll
    for (int k = 0; k < 4; k++) {
        const int pos = atomicAdd(&s_hist[bin_[k]], 1);
        g_spts[b * NN + pos] = pt[k];
        g_sidx[b * NN + pos] = k * 1024 + t;
    }
}

// ---- K2: group-culled main + fused last-block reduction ----
// Split s owns groups {g : g % NSPLIT == s}: every block sees a uniform spatial
// sample -> per-block cull pass-rate ~ global average -> no diagonal-block tail.
__global__ __launch_bounds__(TILE_I, 12)
void steric_fused(float* __restrict__ out) {
    __shared__ __align__(16) float    snx[JCHUNK];
    __shared__ __align__(16) float    sny[JCHUNK];
    __shared__ __align__(16) float    snz[JCHUNK];
    __shared__ __align__(16) uint32_t srh[JPAIRS];
    __shared__ __align__(16) float4   sgb[GPSP];     // (-cx,-cy,-cz, (2+rg)^2)
    __shared__ int s_ticket;

    const int bidx  = blockIdx.x;
    const int split = bidx % NSPLIT;
    const int itile = (bidx / NSPLIT) % (NN / TILE_I);
    const int b     = bidx / (NSPLIT * (NN / TILE_I));
    const int group = b * (NN / TILE_I) + itile;
    const int tid   = threadIdx.x;

    // Stage strided groups: local group lg -> global group (split + NSPLIT*lg).
    for (int k = tid; k < JPAIRS; k += TILE_I) {
        const int lg  = k >> 3;             // 8 pairs per 16-point group
        const int off = (k & 7) * 2;        // element offset within group
        const int j   = b * NN + (split + NSPLIT * lg) * GSZ + off;
        const float4 p0 = g_spts[j];
        const float4 p1 = g_spts[j + 1];
        snx[2 * k] = -p0.x; snx[2 * k + 1] = -p1.x;
        sny[2 * k] = -p0.y; sny[2 * k + 1] = -p1.y;
        snz[2 * k] = -p0.z; snz[2 * k + 1] = -p1.z;
        uint32_t rp;
        CVTH2(rp, p1.w, p0.w);
        srh[k] = rp;
    }
    __syncthreads();

    // In-block group bounds from staged (negated) coords. Exact conservative cull:
    // d(i,C) >= 2+rg  =>  d(i,j) >= 2 > target  =>  pen = 0 for the whole group.
    if (tid < GPSP) {
        const int s0 = tid * GSZ;
        float cx = 0.f, cy = 0.f, cz = 0.f;
        #pragma unroll
        for (int k = 0; k < GSZ; k++) { cx += snx[s0 + k]; cy += sny[s0 + k]; cz += snz[s0 + k]; }
        cx *= (1.0f / GSZ); cy *= (1.0f / GSZ); cz *= (1.0f / GSZ);
        float m2 = 0.f;
        #pragma unroll
        for (int k = 0; k < GSZ; k++) {
            const float dx = snx[s0 + k] - cx, dy = sny[s0 + k] - cy, dz = snz[s0 + k] - cz;
            m2 = fmaxf(m2, dx * dx + dy * dy + dz * dz);
        }
        const float thr = 2.0f + sqrtf(m2) * 1.001f + 1e-3f;    // pad swallows rounding
        sgb[tid] = make_float4(cx, cy, cz, thr * thr);           // negated centroid
    }
    __syncthreads();

    const int is = itile * TILE_I + tid;   // sorted position in batch
    const float4 q = g_spts[b * NN + is];

    unsigned long long xi2, yi2, zi2;
    PACK2(xi2, q.x, q.x);
    PACK2(yi2, q.y, q.y);
    PACK2(zi2, q.z, q.z);
    uint32_t ri2;
    CVTH2(ri2, q.w, q.w);

    const unsigned int anx = (unsigned int)__cvta_generic_to_shared(snx);
    const unsigned int any_ = (unsigned int)__cvta_generic_to_shared(sny);
    const unsigned int anz = (unsigned int)__cvta_generic_to_shared(snz);
    const unsigned int arh = (unsigned int)__cvta_generic_to_shared(srh);

    uint32_t axh = H2_ZERO, ayh = H2_ZERO, azh = H2_ZERO;

    for (int g = 0; g < GPSP; g++) {
        const float4 G = sgb[g];
        const float gx = q.x + G.x, gy = q.y + G.y, gz = q.z + G.z;   // q - centroid
        const float d2c = gx * gx + gy * gy + gz * gz;
        if (d2c >= G.w) continue;

        const int k0 = g * (GSZ / 2);
        #pragma unroll
        for (int kk = k0; kk < k0 + GSZ / 2; kk++) {
            unsigned long long nxp, nyp, nzp;
            LDS64(nxp, anx + 8u * kk);
            LDS64(nyp, any_ + 8u * kk);
            LDS64(nzp, anz + 8u * kk);

            unsigned long long dxp, dyp, dzp, d2p;
            ADD2(dxp, xi2, nxp);
            ADD2(dyp, yi2, nyp);
            ADD2(dzp, zi2, nzp);
            MUL2(d2p, dxp, dxp);
            FMA2(d2p, dyp, dyp, d2p);
            FMA2(d2p, dzp, dzp, d2p);

            float d2lo, d2hi;
            UNPACK2(d2lo, d2hi, d2p);

            // EXACT skip: radii in [0,1) => target < 2 => pen>0 only if d2 < 4.
            if (fminf(d2lo, d2hi) < 4.0f) {
                float dx0, dx1, dy0, dy1, dz0, dz1;
                UNPACK2(dx0, dx1, dxp);
                UNPACK2(dy0, dy1, dyp);
                UNPACK2(dz0, dz1, dzp);

                float d0, d1;
                SQRTA(d0, d2lo);    // sqrt.approx(0)==0: diagonal safe (clip(0)=0)
                SQRTA(d1, d2hi);

                uint32_t dh, dxh, dyh, dzh, rp, t, pen;
                CVTH2(dh,  d1,  d0);
                CVTH2(dxh, dx1, dx0);
                CVTH2(dyh, dy1, dy0);
                CVTH2(dzh, dz1, dz0);
                LDS32(rp, arh + 4u * kk);

                HADD2(t, ri2, rp);
                HMAX2(t, t, H2_ONE);
                HSUB2(pen, t, dh);
                HMAX2(pen, pen, H2_ZERO);

                uint32_t cx, cy, cz;
                HMAX2(cx, dxh, H2_NEG1); HMIN2(cx, cx, H2_ONE);
                HMAX2(cy, dyh, H2_NEG1); HMIN2(cy, cy, H2_ONE);
                HMAX2(cz, dzh, H2_NEG1); HMIN2(cz, cz, H2_ONE);

                HFMA2(axh, pen, cx, axh);
                HFMA2(ayh, pen, cy, ayh);
                HFMA2(azh, pen, cz, azh);
            }
        }
    }

    const __half2 hax = *reinterpret_cast<__half2*>(&axh);
    const __half2 hay = *reinterpret_cast<__half2*>(&ayh);
    const __half2 haz = *reinterpret_cast<__half2*>(&azh);
    const float ax = __low2float(hax) + __high2float(hax);
    const float ay = __low2float(hay) + __high2float(hay);
    const float az = __low2float(haz) + __high2float(haz);

    const size_t idx3 = ((size_t)b * NN + is) * 3;
    float* dst = g_part + (size_t)split * BB * NN * 3 + idx3;
    dst[0] = ax; dst[1] = ay; dst[2] = az;

    // Last-block-done reduction (fixed split order 0..7 -> deterministic given sort).
    __threadfence();
    if (tid == 0) s_ticket = atomicAdd(&g_done[group], 1);
    __syncthreads();
    if (s_ticket == NSPLIT - 1) {
        __threadfence();
        float sx = 0.f, sy = 0.f, sz = 0.f;
        #pragma unroll
        for (int sp = 0; sp < NSPLIT; sp++) {
            const float* p = g_part + (size_t)sp * BB * NN * 3 + idx3;
            sx += p[0]; sy += p[1]; sz += p[2];
        }
        const float k = 0.1f / (float)NN;
        const size_t o3 = ((size_t)b * NN + g_sidx[b * NN + is]) * 3;
        out[o3]     = fmaf(k, sx, q.x);
        out[o3 + 1] = fmaf(k, sy, q.y);
        out[o3 + 2] = fmaf(k, sz, q.z);
        if (tid == 0) g_done[group] = 0;   // reset for next execution
    }
}

extern "C" void kernel_launch(void* const* d_in, const int* in_sizes, int n_in,
                              void* d_out, int out_size) {
    const float* coords = (const float*)d_in[0];
    const float* radii  = (const float*)d_in[1];
    float* out = (float*)d_out;

    int B = in_sizes[1] / NN;   // radii elems = B*N
    if (B < 1) B = 1;
    if (B > BB) B = BB;

    k_sort      <<<B, 1024>>>(coords, radii);
    const int grid = B * (NN / TILE_I) * NSPLIT;
    steric_fused<<<grid, TILE_I>>>(out);
}